// round 3
// baseline (speedup 1.0000x reference)
#include <cuda_runtime.h>
#include <cuda_bf16.h>
#include <cstdint>

#define NN 100000
#define KK 4
#define EE 1600000
#define HH 64
#define FF 256
#define CHUNKS 98   // ceil(N/1024)

// ---------------- scratch (device globals; no runtime alloc) ----------------
__device__ float g_h[(size_t)KK * NN * HH];      // GEMM1 output per expert
__device__ float g_x[(size_t)KK * NN * HH];      // relu(conv1) output
__device__ int   g_deg[KK * NN];
__device__ float g_dis[KK * NN];
__device__ int   g_rowstart[KK * (NN + 1)];
__device__ int   g_cursor[KK * NN];
__device__ int   g_csrc[(size_t)KK * EE];
__device__ float g_h2[(size_t)KK * NN * 2];
__device__ float g_logits[(size_t)KK * NN * 2];
__device__ float g_sums[KK * HH];
__device__ float g_sumsq[KK * HH];
__device__ float g_w2eff[KK * HH * 2];
__device__ float g_c0[KK * 2];
__device__ int   g_partials[KK * CHUNKS];

// ---------------- helpers ----------------
__device__ __forceinline__ uint32_t f2tf(float f) {
    uint32_t u;
    asm("cvt.rna.tf32.f32 %0, %1;" : "=r"(u) : "f"(f));
    return u;
}

// ---------------- init ----------------
__global__ void k_init() {
    int i = blockIdx.x * blockDim.x + threadIdx.x;
    if (i < KK * NN) g_deg[i] = 0;
    if (i < KK * HH) { g_sums[i] = 0.f; g_sumsq[i] = 0.f; }
    if (i < KK) g_rowstart[i * (NN + 1) + NN] = EE;
}

// ---------------- GEMM1: h[k] = flatten @ W1[k]  (tf32 mma.sync) ----------------
// block: 128(M) x 64(N=one expert) x K-tiles of 16; 8 warps (4x2), warp tile 32x32
#define ASTR 20
#define BSTR 72
__global__ __launch_bounds__(256) void k_gemm1(const float* __restrict__ A,
                                               const float* __restrict__ W1) {
    __shared__ float As[128 * ASTR];
    __shared__ float Bs[16 * BSTR];
    int t = threadIdx.x, lane = t & 31, warp = t >> 5;
    int wm = warp & 3, wn = warp >> 2;
    int bm = blockIdx.x, kexp = blockIdx.y;
    const float* Wk = W1 + (size_t)kexp * FF * HH;

    int ar = t >> 2, ac = (t & 3) * 4;      // A: 2 float4 loads (rows ar, ar+64)
    int br = t >> 4, bc = (t & 15) * 4;     // B: 1 float4 load

    float4 rA0, rA1, rB;
    {
        int r0 = bm * 128 + ar, r1 = r0 + 64;
        rA0 = (r0 < NN) ? *(const float4*)(A + (size_t)r0 * FF + ac) : make_float4(0,0,0,0);
        rA1 = (r1 < NN) ? *(const float4*)(A + (size_t)r1 * FF + ac) : make_float4(0,0,0,0);
        rB  = *(const float4*)(Wk + br * HH + bc);
    }

    float c[2][4][4];
#pragma unroll
    for (int mi = 0; mi < 2; mi++)
#pragma unroll
        for (int ni = 0; ni < 4; ni++)
#pragma unroll
            for (int j = 0; j < 4; j++) c[mi][ni][j] = 0.f;

    for (int kt = 0; kt < 16; kt++) {
        *(float4*)(As + ar * ASTR + ac) = rA0;
        *(float4*)(As + (ar + 64) * ASTR + ac) = rA1;
        *(float4*)(Bs + br * BSTR + bc) = rB;
        __syncthreads();

        if (kt < 15) {
            int kn = (kt + 1) * 16;
            int r0 = bm * 128 + ar, r1 = r0 + 64;
            rA0 = (r0 < NN) ? *(const float4*)(A + (size_t)r0 * FF + kn + ac) : make_float4(0,0,0,0);
            rA1 = (r1 < NN) ? *(const float4*)(A + (size_t)r1 * FF + kn + ac) : make_float4(0,0,0,0);
            rB  = *(const float4*)(Wk + (kn + br) * HH + bc);
        }

#pragma unroll
        for (int kk = 0; kk < 16; kk += 8) {
            uint32_t af[2][4], bf[4][2];
#pragma unroll
            for (int mi = 0; mi < 2; mi++) {
                int r = wm * 32 + mi * 16 + (lane >> 2);
                int cc = kk + (lane & 3);
                af[mi][0] = f2tf(As[r * ASTR + cc]);
                af[mi][1] = f2tf(As[(r + 8) * ASTR + cc]);
                af[mi][2] = f2tf(As[r * ASTR + cc + 4]);
                af[mi][3] = f2tf(As[(r + 8) * ASTR + cc + 4]);
            }
#pragma unroll
            for (int ni = 0; ni < 4; ni++) {
                int col = wn * 32 + ni * 8 + (lane >> 2);
                int kr = kk + (lane & 3);
                bf[ni][0] = f2tf(Bs[kr * BSTR + col]);
                bf[ni][1] = f2tf(Bs[(kr + 4) * BSTR + col]);
            }
#pragma unroll
            for (int mi = 0; mi < 2; mi++)
#pragma unroll
                for (int ni = 0; ni < 4; ni++) {
                    asm volatile(
                        "mma.sync.aligned.m16n8k8.row.col.f32.tf32.tf32.f32 "
                        "{%0,%1,%2,%3}, {%4,%5,%6,%7}, {%8,%9}, {%0,%1,%2,%3};"
                        : "+f"(c[mi][ni][0]), "+f"(c[mi][ni][1]),
                          "+f"(c[mi][ni][2]), "+f"(c[mi][ni][3])
                        : "r"(af[mi][0]), "r"(af[mi][1]), "r"(af[mi][2]), "r"(af[mi][3]),
                          "r"(bf[ni][0]), "r"(bf[ni][1]));
                }
        }
        __syncthreads();
    }

    float* hk = g_h + (size_t)kexp * NN * HH;
#pragma unroll
    for (int mi = 0; mi < 2; mi++)
#pragma unroll
        for (int ni = 0; ni < 4; ni++) {
            int r0 = bm * 128 + wm * 32 + mi * 16 + (lane >> 2);
            int col = wn * 32 + ni * 8 + (lane & 3) * 2;
            if (r0 < NN) *(float2*)(hk + (size_t)r0 * HH + col) = make_float2(c[mi][ni][0], c[mi][ni][1]);
            int r1 = r0 + 8;
            if (r1 < NN) *(float2*)(hk + (size_t)r1 * HH + col) = make_float2(c[mi][ni][2], c[mi][ni][3]);
        }
}

// ---------------- degree histogram ----------------
__global__ void k_deg(const int* __restrict__ ei) {
    int k = blockIdx.y;
    int e = blockIdx.x * blockDim.x + threadIdx.x;
    if (e >= EE) return;
    int dst = ei[(size_t)k * 2 * EE + EE + e];
    atomicAdd(&g_deg[k * NN + dst], 1);
}

// ---------------- exclusive scan of deg (3 kernels) ----------------
__global__ void k_scanA() {
    int k = blockIdx.y, chunk = blockIdx.x, t = threadIdx.x;
    int n0 = chunk * 1024 + t * 4;
    int s = 0;
#pragma unroll
    for (int i = 0; i < 4; i++) { int n = n0 + i; if (n < NN) s += g_deg[k * NN + n]; }
    for (int off = 16; off; off >>= 1) s += __shfl_down_sync(0xffffffffu, s, off);
    __shared__ int ws[8];
    if ((t & 31) == 0) ws[t >> 5] = s;
    __syncthreads();
    if (t == 0) {
        int tot = 0;
        for (int i = 0; i < 8; i++) tot += ws[i];
        g_partials[k * CHUNKS + chunk] = tot;
    }
}

__global__ void k_scanB() {
    int t = threadIdx.x;  // 128
    __shared__ int sm[128];
    for (int k = 0; k < KK; k++) {
        int p = (t < CHUNKS) ? g_partials[k * CHUNKS + t] : 0;
        sm[t] = p; __syncthreads();
        for (int off = 1; off < 128; off <<= 1) {
            int a = (t >= off) ? sm[t - off] : 0;
            __syncthreads();
            sm[t] += a;
            __syncthreads();
        }
        if (t < CHUNKS) g_partials[k * CHUNKS + t] = sm[t] - p;  // exclusive
        __syncthreads();
    }
}

__global__ void k_scanC() {
    int k = blockIdx.y, chunk = blockIdx.x, t = threadIdx.x;
    int lane = t & 31, wid = t >> 5;
    int n0 = chunk * 1024 + t * 4;
    int v[4];
#pragma unroll
    for (int i = 0; i < 4; i++) { int n = n0 + i; v[i] = (n < NN) ? g_deg[k * NN + n] : 0; }
    int s0 = v[0], s1 = s0 + v[1], s2 = s1 + v[2], s3 = s2 + v[3];
    int x = s3;
    for (int off = 1; off < 32; off <<= 1) {
        int y = __shfl_up_sync(0xffffffffu, x, off);
        if (lane >= off) x += y;
    }
    __shared__ int ws[8];
    if (lane == 31) ws[wid] = x;
    __syncthreads();
    if (t < 8) {
        int w = ws[t];
        for (int off = 1; off < 8; off <<= 1) {
            int y = __shfl_up_sync(0xffu, w, off);
            if (t >= off) w += y;
        }
        ws[t] = w;
    }
    __syncthreads();
    int excl = ((wid == 0) ? 0 : ws[wid - 1]) + (x - s3);
    int gbase = g_partials[k * CHUNKS + chunk] + excl;
    int pre[4] = {0, s0, s1, s2};
#pragma unroll
    for (int i = 0; i < 4; i++) {
        int n = n0 + i;
        if (n < NN) {
            int rs = gbase + pre[i];
            g_rowstart[k * (NN + 1) + n] = rs;
            g_cursor[k * NN + n] = rs;
            g_dis[k * NN + n] = rsqrtf((float)v[i] + 2.0f);
        }
    }
}

// ---------------- CSR fill ----------------
__global__ void k_csr(const int* __restrict__ ei) {
    int k = blockIdx.y;
    int e = blockIdx.x * blockDim.x + threadIdx.x;
    if (e >= EE) return;
    int src = ei[(size_t)k * 2 * EE + e];
    int dst = ei[(size_t)k * 2 * EE + EE + e];
    int pos = atomicAdd(&g_cursor[k * NN + dst], 1);
    g_csrc[(size_t)k * EE + pos] = src;
}

// ---------------- conv1 aggregate + bias + relu -> x ----------------
__global__ __launch_bounds__(256) void k_agg1(const float* __restrict__ b1) {
    int k = blockIdx.y;
    int lane = threadIdx.x & 31;
    int node = blockIdx.x * 8 + (threadIdx.x >> 5);
    if (node >= NN) return;
    const float* hk = g_h + (size_t)k * NN * HH;
    const int* cs = g_csrc + (size_t)k * EE;
    const float* dk = g_dis + k * NN;
    int base = g_rowstart[k * (NN + 1) + node];
    int end  = g_rowstart[k * (NN + 1) + node + 1];
    float ax = 0.f, ay = 0.f;
    for (int i = base; i < end; i += 32) {
        int e = i + lane;
        int s = 0; float d = 0.f;
        if (e < end) { s = cs[e]; d = dk[s]; }
        int cnt = min(32, end - i);
        for (int j = 0; j < cnt; j++) {
            int sj = __shfl_sync(0xffffffffu, s, j);
            float dj = __shfl_sync(0xffffffffu, d, j);
            float2 hv = *(const float2*)(hk + (size_t)sj * HH + 2 * lane);
            ax += hv.x * dj;
            ay += hv.y * dj;
        }
    }
    float dn = dk[node];
    float2 hn = *(const float2*)(hk + (size_t)node * HH + 2 * lane);
    float sx = ax * dn + 2.f * dn * dn * hn.x + b1[k * HH + 2 * lane];
    float sy = ay * dn + 2.f * dn * dn * hn.y + b1[k * HH + 2 * lane + 1];
    sx = fmaxf(sx, 0.f);
    sy = fmaxf(sy, 0.f);
    *(float2*)(g_x + ((size_t)k * NN + node) * HH + 2 * lane) = make_float2(sx, sy);
}

// ---------------- layernorm reduction (per-feature over nodes) ----------------
__global__ void k_lnreduce() {
    int k = blockIdx.y, chunk = blockIdx.x, t = threadIdx.x;
    __shared__ float ss[64], sq[64];
    if (t < 64) { ss[t] = 0.f; sq[t] = 0.f; }
    __syncthreads();
    size_t base = ((size_t)k * NN + (size_t)chunk * 1024) * HH;
    int maxL = (NN - chunk * 1024) * HH;
    if (maxL > 1024 * HH) maxL = 1024 * HH;
    float s = 0.f, q = 0.f;
    for (int L = t; L < maxL; L += 256) {
        float v = g_x[base + L];
        s += v; q += v * v;
    }
    atomicAdd(&ss[t & 63], s);
    atomicAdd(&sq[t & 63], q);
    __syncthreads();
    if (t < 64) atomicAdd(&g_sums[k * HH + t], ss[t]);
    else if (t < 128) atomicAdd(&g_sumsq[k * HH + t - 64], sq[t - 64]);
}

// ---------------- fold LN into W2: w2eff = s*W2, c0 = t @ W2 ----------------
__global__ void k_lnfinal(const float* __restrict__ gamma, const float* __restrict__ beta,
                          const float* __restrict__ W2) {
    int t = threadIdx.x;  // 256
    int k = t >> 6, f = t & 63;
    float mu = g_sums[k * HH + f] / (float)NN;
    float var = g_sumsq[k * HH + f] / (float)NN - mu * mu;
    float inv = rsqrtf(var + 1e-5f);
    float s = inv * gamma[k * HH + f];
    float tt = beta[k * HH + f] - mu * s;
    float w0 = W2[k * HH * 2 + f * 2 + 0];
    float w1 = W2[k * HH * 2 + f * 2 + 1];
    g_w2eff[k * HH * 2 + f * 2 + 0] = s * w0;
    g_w2eff[k * HH * 2 + f * 2 + 1] = s * w1;
    __shared__ float red[256];
    red[t] = tt * w0; __syncthreads();
    for (int off = 32; off >= 1; off >>= 1) { if (f < off) red[t] += red[t + off]; __syncthreads(); }
    if (f == 0) g_c0[k * 2 + 0] = red[t];
    __syncthreads();
    red[t] = tt * w1; __syncthreads();
    for (int off = 32; off >= 1; off >>= 1) { if (f < off) red[t] += red[t + off]; __syncthreads(); }
    if (f == 0) g_c0[k * 2 + 1] = red[t];
}

// ---------------- h2 = relu_x @ w2eff + c0 ----------------
__global__ void k_h2() {
    int k = blockIdx.y;
    int t = threadIdx.x;
    __shared__ float w_s[128];
    __shared__ float c0s[2];
    if (t < 128) w_s[t] = g_w2eff[k * 128 + t];
    if (t < 2) c0s[t] = g_c0[k * 2 + t];
    __syncthreads();
    int n = blockIdx.x * blockDim.x + t;
    if (n >= NN) return;
    const float* xr = g_x + ((size_t)k * NN + n) * HH;
    float a0 = c0s[0], a1 = c0s[1];
#pragma unroll
    for (int f = 0; f < 64; f += 4) {
        float4 xv = *(const float4*)(xr + f);
        a0 += xv.x * w_s[f * 2]     + xv.y * w_s[f * 2 + 2] + xv.z * w_s[f * 2 + 4] + xv.w * w_s[f * 2 + 6];
        a1 += xv.x * w_s[f * 2 + 1] + xv.y * w_s[f * 2 + 3] + xv.z * w_s[f * 2 + 5] + xv.w * w_s[f * 2 + 7];
    }
    g_h2[((size_t)k * NN + n) * 2 + 0] = a0;
    g_h2[((size_t)k * NN + n) * 2 + 1] = a1;
}

// ---------------- conv2 aggregate -> logits ----------------
__global__ void k_agg2(const float* __restrict__ b2) {
    int k = blockIdx.y;
    int n = blockIdx.x * blockDim.x + threadIdx.x;
    if (n >= NN) return;
    int base = g_rowstart[k * (NN + 1) + n];
    int end  = g_rowstart[k * (NN + 1) + n + 1];
    const int* cs = g_csrc + (size_t)k * EE;
    const float* dk = g_dis + k * NN;
    const float2* h2k = (const float2*)(g_h2 + (size_t)k * NN * 2);
    float a0 = 0.f, a1 = 0.f;
    for (int e = base; e < end; e++) {
        int s = cs[e];
        float d = dk[s];
        float2 hv = h2k[s];
        a0 += hv.x * d;
        a1 += hv.y * d;
    }
    float dn = dk[n];
    float2 hn = h2k[n];
    a0 = a0 * dn + 2.f * dn * dn * hn.x + b2[k * 2 + 0];
    a1 = a1 * dn + 2.f * dn * dn * hn.y + b2[k * 2 + 1];
    g_logits[((size_t)k * NN + n) * 2 + 0] = a0;
    g_logits[((size_t)k * NN + n) * 2 + 1] = a1;
}

// ---------------- gating + softmax mix ----------------
__global__ __launch_bounds__(256) void k_final(const float* __restrict__ mf,
                                               const float* __restrict__ Wg,
                                               const float* __restrict__ bg,
                                               float* __restrict__ out) {
    __shared__ float wg_s[FF * KK];
    __shared__ float bg_s[KK];
    int t = threadIdx.x;
    for (int i = t; i < FF * KK; i += 256) wg_s[i] = Wg[i];
    if (t < KK) bg_s[t] = bg[t];
    __syncthreads();
    int lane = t & 31;
    int node = blockIdx.x * 8 + (t >> 5);
    if (node >= NN) return;
    const float* row = mf + (size_t)node * FF;
    float a0 = 0.f, a1 = 0.f, a2 = 0.f, a3 = 0.f;
#pragma unroll
    for (int j = 0; j < 8; j++) {
        float v = row[lane + 32 * j];
        const float* w = &wg_s[(lane + 32 * j) * 4];
        a0 += v * w[0]; a1 += v * w[1]; a2 += v * w[2]; a3 += v * w[3];
    }
    for (int off = 16; off; off >>= 1) {
        a0 += __shfl_xor_sync(0xffffffffu, a0, off);
        a1 += __shfl_xor_sync(0xffffffffu, a1, off);
        a2 += __shfl_xor_sync(0xffffffffu, a2, off);
        a3 += __shfl_xor_sync(0xffffffffu, a3, off);
    }
    float l0 = a0 + bg_s[0], l1 = a1 + bg_s[1], l2 = a2 + bg_s[2], l3 = a3 + bg_s[3];
    float m = fmaxf(fmaxf(l0, l1), fmaxf(l2, l3));
    float e0 = expf(l0 - m), e1 = expf(l1 - m), e2 = expf(l2 - m), e3 = expf(l3 - m);
    float Z = e0 + e1 + e2 + e3;
    float wk[4] = {e0 / Z, e1 / Z, e2 / Z, e3 / Z};
    float r0 = 0.f, r1 = 0.f, p0 = 0.f, p1 = 0.f;
#pragma unroll
    for (int k = 0; k < KK; k++) {
        float la = g_logits[((size_t)k * NN + node) * 2 + 0];
        float lb = g_logits[((size_t)k * NN + node) * 2 + 1];
        float mm = fmaxf(la, lb);
        float ea = expf(la - mm), eb = expf(lb - mm);
        float z = ea + eb;
        float lse = mm + logf(z);
        r0 += wk[k] * (la - lse);
        r1 += wk[k] * (lb - lse);
        p0 += wk[k] * (ea / z);
        p1 += wk[k] * (eb / z);
    }
    if (lane == 0) {
        out[(size_t)node * 2 + 0] = r0;
        out[(size_t)node * 2 + 1] = r1;
        out[(size_t)2 * NN + node * 2 + 0] = p0;
        out[(size_t)2 * NN + node * 2 + 1] = p1;
    }
}

// ---------------- launch ----------------
extern "C" void kernel_launch(void* const* d_in, const int* in_sizes, int n_in,
                              void* d_out, int out_size) {
    const float* flatten = (const float*)d_in[0];
    const float* moe     = (const float*)d_in[1];
    const int*   ei      = (const int*)d_in[2];
    const float* W1      = (const float*)d_in[3];
    const float* b1      = (const float*)d_in[4];
    const float* gamma   = (const float*)d_in[5];
    const float* beta    = (const float*)d_in[6];
    const float* W2      = (const float*)d_in[7];
    const float* b2      = (const float*)d_in[8];
    const float* Wg      = (const float*)d_in[9];
    const float* bg      = (const float*)d_in[10];
    float* out = (float*)d_out;

    k_init<<<(KK * NN + 255) / 256, 256>>>();
    k_gemm1<<<dim3((NN + 127) / 128, KK), 256>>>(flatten, W1);
    k_deg<<<dim3((EE + 255) / 256, KK), 256>>>(ei);
    k_scanA<<<dim3(CHUNKS, KK), 256>>>();
    k_scanB<<<1, 128>>>();
    k_scanC<<<dim3(CHUNKS, KK), 256>>>();
    k_csr<<<dim3((EE + 255) / 256, KK), 256>>>(ei);
    k_agg1<<<dim3((NN + 7) / 8, KK), 256>>>(b1);
    k_lnreduce<<<dim3(CHUNKS, KK), 256>>>();
    k_lnfinal<<<1, 256>>>(gamma, beta, W2);
    k_h2<<<dim3((NN + 255) / 256, KK), 256>>>();
    k_agg2<<<dim3((NN + 255) / 256, KK), 256>>>(b2);
    k_final<<<(NN + 7) / 8, 256>>>(moe, Wg, bg, out);
}

// round 4
// speedup vs baseline: 1.1992x; 1.1992x over previous
#include <cuda_runtime.h>
#include <cuda_bf16.h>
#include <cstdint>

#define NN 100000
#define KK 4
#define EE 1600000
#define HH 64
#define FF 256
#define CHUNKS 98   // ceil(N/1024)

// ---------------- scratch (device globals; no runtime alloc) ----------------
__device__ float g_h[(size_t)KK * NN * HH];      // h' = dis * (flatten @ W1)  per expert
__device__ float g_x[(size_t)KK * NN * HH];      // relu(conv1) output
__device__ int   g_deg[KK * NN];
__device__ float g_dis[KK * NN];
__device__ int   g_rowstart[KK * (NN + 1)];
__device__ int   g_cursor[KK * NN];
__device__ int   g_csrc[(size_t)KK * EE];
__device__ float g_h2[(size_t)KK * NN * 2];      // h2' = dis * (x @ w2eff + c0)
__device__ float g_logits[(size_t)KK * NN * 2];
__device__ float g_sums[KK * HH];
__device__ float g_sumsq[KK * HH];
__device__ float g_w2eff[KK * HH * 2];
__device__ float g_c0[KK * 2];
__device__ int   g_partials[KK * CHUNKS];

// ---------------- helpers ----------------
__device__ __forceinline__ uint32_t f2tf(float f) {
    uint32_t u;
    asm("cvt.rna.tf32.f32 %0, %1;" : "=r"(u) : "f"(f));
    return u;
}

// ---------------- init ----------------
__global__ void k_init() {
    int i = blockIdx.x * blockDim.x + threadIdx.x;
    if (i < KK * NN) g_deg[i] = 0;
    if (i < KK * HH) { g_sums[i] = 0.f; g_sumsq[i] = 0.f; }
    if (i < KK) g_rowstart[i * (NN + 1) + NN] = EE;
}

// ---------------- degree histogram ----------------
__global__ void k_deg(const int* __restrict__ ei) {
    int k = blockIdx.y;
    int e = blockIdx.x * blockDim.x + threadIdx.x;
    if (e >= EE) return;
    int dst = ei[(size_t)k * 2 * EE + EE + e];
    atomicAdd(&g_deg[k * NN + dst], 1);
}

// ---------------- exclusive scan of deg (3 kernels) ----------------
__global__ void k_scanA() {
    int k = blockIdx.y, chunk = blockIdx.x, t = threadIdx.x;
    int n0 = chunk * 1024 + t * 4;
    int s = 0;
#pragma unroll
    for (int i = 0; i < 4; i++) { int n = n0 + i; if (n < NN) s += g_deg[k * NN + n]; }
    for (int off = 16; off; off >>= 1) s += __shfl_down_sync(0xffffffffu, s, off);
    __shared__ int ws[8];
    if ((t & 31) == 0) ws[t >> 5] = s;
    __syncthreads();
    if (t == 0) {
        int tot = 0;
        for (int i = 0; i < 8; i++) tot += ws[i];
        g_partials[k * CHUNKS + chunk] = tot;
    }
}

__global__ void k_scanB() {
    int t = threadIdx.x;  // 128
    __shared__ int sm[128];
    for (int k = 0; k < KK; k++) {
        int p = (t < CHUNKS) ? g_partials[k * CHUNKS + t] : 0;
        sm[t] = p; __syncthreads();
        for (int off = 1; off < 128; off <<= 1) {
            int a = (t >= off) ? sm[t - off] : 0;
            __syncthreads();
            sm[t] += a;
            __syncthreads();
        }
        if (t < CHUNKS) g_partials[k * CHUNKS + t] = sm[t] - p;  // exclusive
        __syncthreads();
    }
}

__global__ void k_scanC() {
    int k = blockIdx.y, chunk = blockIdx.x, t = threadIdx.x;
    int lane = t & 31, wid = t >> 5;
    int n0 = chunk * 1024 + t * 4;
    int v[4];
#pragma unroll
    for (int i = 0; i < 4; i++) { int n = n0 + i; v[i] = (n < NN) ? g_deg[k * NN + n] : 0; }
    int s0 = v[0], s1 = s0 + v[1], s2 = s1 + v[2], s3 = s2 + v[3];
    int x = s3;
    for (int off = 1; off < 32; off <<= 1) {
        int y = __shfl_up_sync(0xffffffffu, x, off);
        if (lane >= off) x += y;
    }
    __shared__ int ws[8];
    if (lane == 31) ws[wid] = x;
    __syncthreads();
    if (t < 8) {
        int w = ws[t];
        for (int off = 1; off < 8; off <<= 1) {
            int y = __shfl_up_sync(0xffu, w, off);
            if (t >= off) w += y;
        }
        ws[t] = w;
    }
    __syncthreads();
    int excl = ((wid == 0) ? 0 : ws[wid - 1]) + (x - s3);
    int gbase = g_partials[k * CHUNKS + chunk] + excl;
    int pre[4] = {0, s0, s1, s2};
#pragma unroll
    for (int i = 0; i < 4; i++) {
        int n = n0 + i;
        if (n < NN) {
            int rs = gbase + pre[i];
            g_rowstart[k * (NN + 1) + n] = rs;
            g_cursor[k * NN + n] = rs;
            g_dis[k * NN + n] = rsqrtf((float)v[i] + 2.0f);
        }
    }
}

// ---------------- GEMM1: h'[k] = dis[k] * (flatten @ W1[k])  (tf32 mma.sync) ----
// block 128(M) x 256(N = all 4 experts) x K-tiles of 16; 16 warps (4x4), warp 32x64
#define ASTR 20
#define BSTR 264
__global__ __launch_bounds__(512) void k_gemm1(const float* __restrict__ A,
                                               const float* __restrict__ W1) {
    __shared__ float As[128 * ASTR];
    __shared__ float Bs[16 * BSTR];
    int t = threadIdx.x, lane = t & 31, warp = t >> 5;
    int wm = warp & 3, wn = warp >> 2;     // wn = expert index (warp n-tile = 64 = one expert)
    int bm = blockIdx.x;

    int ar = t >> 2, ac = (t & 3) * 4;     // A: 1 float4 per thread per tile
    // B: 2 float4 per thread per tile; idx in [0,1024): row = idx>>6, cq = (idx&63)*4
    int b0r = t >> 6,          b0q = (t & 63) * 4;
    int b1r = (t + 512) >> 6,  b1q = (t & 63) * 4;
    int b0k = b0q >> 6, b0h = b0q & 63;
    int b1k = b1q >> 6, b1h = b1q & 63;

    float4 rA, rB0, rB1;
    {
        int r0 = bm * 128 + ar;
        rA  = (r0 < NN) ? *(const float4*)(A + (size_t)r0 * FF + ac) : make_float4(0,0,0,0);
        rB0 = *(const float4*)(W1 + ((size_t)b0k * FF + b0r) * HH + b0h);
        rB1 = *(const float4*)(W1 + ((size_t)b1k * FF + b1r) * HH + b1h);
    }

    float c[2][8][4];
#pragma unroll
    for (int mi = 0; mi < 2; mi++)
#pragma unroll
        for (int ni = 0; ni < 8; ni++)
#pragma unroll
            for (int j = 0; j < 4; j++) c[mi][ni][j] = 0.f;

    for (int kt = 0; kt < 16; kt++) {
        *(float4*)(As + ar * ASTR + ac) = rA;
        *(float4*)(Bs + b0r * BSTR + b0q) = rB0;
        *(float4*)(Bs + b1r * BSTR + b1q) = rB1;
        __syncthreads();

        if (kt < 15) {
            int kn = (kt + 1) * 16;
            int r0 = bm * 128 + ar;
            rA  = (r0 < NN) ? *(const float4*)(A + (size_t)r0 * FF + kn + ac) : make_float4(0,0,0,0);
            rB0 = *(const float4*)(W1 + ((size_t)b0k * FF + kn + b0r) * HH + b0h);
            rB1 = *(const float4*)(W1 + ((size_t)b1k * FF + kn + b1r) * HH + b1h);
        }

#pragma unroll
        for (int kk = 0; kk < 16; kk += 8) {
            uint32_t af[2][4], bf[8][2];
#pragma unroll
            for (int mi = 0; mi < 2; mi++) {
                int r = wm * 32 + mi * 16 + (lane >> 2);
                int cc = kk + (lane & 3);
                af[mi][0] = f2tf(As[r * ASTR + cc]);
                af[mi][1] = f2tf(As[(r + 8) * ASTR + cc]);
                af[mi][2] = f2tf(As[r * ASTR + cc + 4]);
                af[mi][3] = f2tf(As[(r + 8) * ASTR + cc + 4]);
            }
#pragma unroll
            for (int ni = 0; ni < 8; ni++) {
                int col = wn * 64 + ni * 8 + (lane >> 2);
                int kr = kk + (lane & 3);
                bf[ni][0] = f2tf(Bs[kr * BSTR + col]);
                bf[ni][1] = f2tf(Bs[(kr + 4) * BSTR + col]);
            }
#pragma unroll
            for (int mi = 0; mi < 2; mi++)
#pragma unroll
                for (int ni = 0; ni < 8; ni++) {
                    asm volatile(
                        "mma.sync.aligned.m16n8k8.row.col.f32.tf32.tf32.f32 "
                        "{%0,%1,%2,%3}, {%4,%5,%6,%7}, {%8,%9}, {%0,%1,%2,%3};"
                        : "+f"(c[mi][ni][0]), "+f"(c[mi][ni][1]),
                          "+f"(c[mi][ni][2]), "+f"(c[mi][ni][3])
                        : "r"(af[mi][0]), "r"(af[mi][1]), "r"(af[mi][2]), "r"(af[mi][3]),
                          "r"(bf[ni][0]), "r"(bf[ni][1]));
                }
        }
        __syncthreads();
    }

    // epilogue: scale rows by dis[expert][row], expert = wn
    float* hk = g_h + (size_t)wn * NN * HH;
    const float* dk = g_dis + wn * NN;
#pragma unroll
    for (int mi = 0; mi < 2; mi++) {
        int r0 = bm * 128 + wm * 32 + mi * 16 + (lane >> 2);
        int r1 = r0 + 8;
        float s0 = (r0 < NN) ? dk[r0] : 0.f;
        float s1 = (r1 < NN) ? dk[r1] : 0.f;
#pragma unroll
        for (int ni = 0; ni < 8; ni++) {
            int col = ni * 8 + (lane & 3) * 2;   // within-expert feature
            if (r0 < NN) *(float2*)(hk + (size_t)r0 * HH + col) =
                make_float2(c[mi][ni][0] * s0, c[mi][ni][1] * s0);
            if (r1 < NN) *(float2*)(hk + (size_t)r1 * HH + col) =
                make_float2(c[mi][ni][2] * s1, c[mi][ni][3] * s1);
        }
    }
}

// ---------------- CSR fill ----------------
__global__ void k_csr(const int* __restrict__ ei) {
    int k = blockIdx.y;
    int e = blockIdx.x * blockDim.x + threadIdx.x;
    if (e >= EE) return;
    int src = ei[(size_t)k * 2 * EE + e];
    int dst = ei[(size_t)k * 2 * EE + EE + e];
    int pos = atomicAdd(&g_cursor[k * NN + dst], 1);
    g_csrc[(size_t)k * EE + pos] = src;
}

// ------- conv1 aggregate + bias + relu -> x, with fused LN stats -------
// warp per node-quad: each warp handles 4 nodes, lane owns features 2l, 2l+1
__global__ __launch_bounds__(256) void k_agg1(const float* __restrict__ b1) {
    int k = blockIdx.y;
    int t = threadIdx.x, lane = t & 31, warp = t >> 5;
    __shared__ float ss[64], sq[64];
    if (t < 64) { ss[t] = 0.f; sq[t] = 0.f; }
    __syncthreads();
    const float* hk = g_h + (size_t)k * NN * HH;
    const int* cs = g_csrc + (size_t)k * EE;
    const int* rs = g_rowstart + k * (NN + 1);
    const float* dk = g_dis + k * NN;
    float bx = b1[k * HH + 2 * lane];
    float by = b1[k * HH + 2 * lane + 1];
    float ls0 = 0.f, ls1 = 0.f, lq0 = 0.f, lq1 = 0.f;

#pragma unroll
    for (int i = 0; i < 4; i++) {
        int node = blockIdx.x * 32 + warp * 4 + i;
        if (node >= NN) break;
        int base = rs[node], end = rs[node + 1];
        float ax = 0.f, ay = 0.f;
        for (int i0 = base; i0 < end; i0 += 32) {
            int e = i0 + lane;
            int s = (e < end) ? cs[e] : 0;
            int cnt = min(32, end - i0);
            for (int j = 0; j < cnt; j++) {
                int sj = __shfl_sync(0xffffffffu, s, j);
                float2 hv = *(const float2*)(hk + (size_t)sj * HH + 2 * lane);
                ax += hv.x;
                ay += hv.y;
            }
        }
        float dn = dk[node];
        float2 hn = *(const float2*)(hk + (size_t)node * HH + 2 * lane);
        float sx = fmaxf(dn * (ax + 2.f * hn.x) + bx, 0.f);
        float sy = fmaxf(dn * (ay + 2.f * hn.y) + by, 0.f);
        *(float2*)(g_x + ((size_t)k * NN + node) * HH + 2 * lane) = make_float2(sx, sy);
        ls0 += sx; lq0 += sx * sx;
        ls1 += sy; lq1 += sy * sy;
    }
    atomicAdd(&ss[2 * lane], ls0);
    atomicAdd(&ss[2 * lane + 1], ls1);
    atomicAdd(&sq[2 * lane], lq0);
    atomicAdd(&sq[2 * lane + 1], lq1);
    __syncthreads();
    if (t < 64) atomicAdd(&g_sums[k * HH + t], ss[t]);
    else if (t < 128) atomicAdd(&g_sumsq[k * HH + t - 64], sq[t - 64]);
}

// ---------------- fold LN into W2: w2eff = s*W2, c0 = t @ W2 ----------------
__global__ void k_lnfinal(const float* __restrict__ gamma, const float* __restrict__ beta,
                          const float* __restrict__ W2) {
    int t = threadIdx.x;  // 256
    int k = t >> 6, f = t & 63;
    float mu = g_sums[k * HH + f] / (float)NN;
    float var = g_sumsq[k * HH + f] / (float)NN - mu * mu;
    float inv = rsqrtf(var + 1e-5f);
    float s = inv * gamma[k * HH + f];
    float tt = beta[k * HH + f] - mu * s;
    float w0 = W2[k * HH * 2 + f * 2 + 0];
    float w1 = W2[k * HH * 2 + f * 2 + 1];
    g_w2eff[k * HH * 2 + f * 2 + 0] = s * w0;
    g_w2eff[k * HH * 2 + f * 2 + 1] = s * w1;
    __shared__ float red[256];
    red[t] = tt * w0; __syncthreads();
    for (int off = 32; off >= 1; off >>= 1) { if (f < off) red[t] += red[t + off]; __syncthreads(); }
    if (f == 0) g_c0[k * 2 + 0] = red[t];
    __syncthreads();
    red[t] = tt * w1; __syncthreads();
    for (int off = 32; off >= 1; off >>= 1) { if (f < off) red[t] += red[t + off]; __syncthreads(); }
    if (f == 0) g_c0[k * 2 + 1] = red[t];
}

// ---------------- h2' = dis * (relu_x @ w2eff + c0) ----------------
__global__ void k_h2() {
    int k = blockIdx.y;
    int t = threadIdx.x;
    __shared__ float w_s[128];
    __shared__ float c0s[2];
    if (t < 128) w_s[t] = g_w2eff[k * 128 + t];
    if (t < 2) c0s[t] = g_c0[k * 2 + t];
    __syncthreads();
    int n = blockIdx.x * blockDim.x + t;
    if (n >= NN) return;
    const float* xr = g_x + ((size_t)k * NN + n) * HH;
    float a0 = c0s[0], a1 = c0s[1];
#pragma unroll
    for (int f = 0; f < 64; f += 4) {
        float4 xv = *(const float4*)(xr + f);
        a0 += xv.x * w_s[f * 2]     + xv.y * w_s[f * 2 + 2] + xv.z * w_s[f * 2 + 4] + xv.w * w_s[f * 2 + 6];
        a1 += xv.x * w_s[f * 2 + 1] + xv.y * w_s[f * 2 + 3] + xv.z * w_s[f * 2 + 5] + xv.w * w_s[f * 2 + 7];
    }
    float dn = g_dis[k * NN + n];
    g_h2[((size_t)k * NN + n) * 2 + 0] = a0 * dn;
    g_h2[((size_t)k * NN + n) * 2 + 1] = a1 * dn;
}

// ---------------- conv2 aggregate -> logits ----------------
__global__ void k_agg2(const float* __restrict__ b2) {
    int k = blockIdx.y;
    int n = blockIdx.x * blockDim.x + threadIdx.x;
    if (n >= NN) return;
    int base = g_rowstart[k * (NN + 1) + n];
    int end  = g_rowstart[k * (NN + 1) + n + 1];
    const int* cs = g_csrc + (size_t)k * EE;
    const float2* h2k = (const float2*)(g_h2 + (size_t)k * NN * 2);
    float a0 = 0.f, a1 = 0.f;
    for (int e = base; e < end; e++) {
        float2 hv = h2k[cs[e]];
        a0 += hv.x;
        a1 += hv.y;
    }
    float dn = g_dis[k * NN + n];
    float2 hn = h2k[n];
    a0 = dn * (a0 + 2.f * hn.x) + b2[k * 2 + 0];
    a1 = dn * (a1 + 2.f * hn.y) + b2[k * 2 + 1];
    g_logits[((size_t)k * NN + n) * 2 + 0] = a0;
    g_logits[((size_t)k * NN + n) * 2 + 1] = a1;
}

// ---------------- gating + softmax mix ----------------
__global__ __launch_bounds__(256) void k_final(const float* __restrict__ mf,
                                               const float* __restrict__ Wg,
                                               const float* __restrict__ bg,
                                               float* __restrict__ out) {
    __shared__ float wg_s[FF * KK];
    __shared__ float bg_s[KK];
    int t = threadIdx.x;
    for (int i = t; i < FF * KK; i += 256) wg_s[i] = Wg[i];
    if (t < KK) bg_s[t] = bg[t];
    __syncthreads();
    int lane = t & 31;
    int node = blockIdx.x * 8 + (t >> 5);
    if (node >= NN) return;
    const float* row = mf + (size_t)node * FF;
    float a0 = 0.f, a1 = 0.f, a2 = 0.f, a3 = 0.f;
#pragma unroll
    for (int j = 0; j < 8; j++) {
        float v = row[lane + 32 * j];
        const float* w = &wg_s[(lane + 32 * j) * 4];
        a0 += v * w[0]; a1 += v * w[1]; a2 += v * w[2]; a3 += v * w[3];
    }
    for (int off = 16; off; off >>= 1) {
        a0 += __shfl_xor_sync(0xffffffffu, a0, off);
        a1 += __shfl_xor_sync(0xffffffffu, a1, off);
        a2 += __shfl_xor_sync(0xffffffffu, a2, off);
        a3 += __shfl_xor_sync(0xffffffffu, a3, off);
    }
    float l0 = a0 + bg_s[0], l1 = a1 + bg_s[1], l2 = a2 + bg_s[2], l3 = a3 + bg_s[3];
    float m = fmaxf(fmaxf(l0, l1), fmaxf(l2, l3));
    float e0 = expf(l0 - m), e1 = expf(l1 - m), e2 = expf(l2 - m), e3 = expf(l3 - m);
    float Z = e0 + e1 + e2 + e3;
    float wk[4] = {e0 / Z, e1 / Z, e2 / Z, e3 / Z};
    float r0 = 0.f, r1 = 0.f, p0 = 0.f, p1 = 0.f;
#pragma unroll
    for (int k = 0; k < KK; k++) {
        float la = g_logits[((size_t)k * NN + node) * 2 + 0];
        float lb = g_logits[((size_t)k * NN + node) * 2 + 1];
        float mm = fmaxf(la, lb);
        float ea = expf(la - mm), eb = expf(lb - mm);
        float z = ea + eb;
        float lse = mm + logf(z);
        r0 += wk[k] * (la - lse);
        r1 += wk[k] * (lb - lse);
        p0 += wk[k] * (ea / z);
        p1 += wk[k] * (eb / z);
    }
    if (lane == 0) {
        out[(size_t)node * 2 + 0] = r0;
        out[(size_t)node * 2 + 1] = r1;
        out[(size_t)2 * NN + node * 2 + 0] = p0;
        out[(size_t)2 * NN + node * 2 + 1] = p1;
    }
}

// ---------------- launch ----------------
extern "C" void kernel_launch(void* const* d_in, const int* in_sizes, int n_in,
                              void* d_out, int out_size) {
    const float* flatten = (const float*)d_in[0];
    const float* moe     = (const float*)d_in[1];
    const int*   ei      = (const int*)d_in[2];
    const float* W1      = (const float*)d_in[3];
    const float* b1      = (const float*)d_in[4];
    const float* gamma   = (const float*)d_in[5];
    const float* beta    = (const float*)d_in[6];
    const float* W2      = (const float*)d_in[7];
    const float* b2      = (const float*)d_in[8];
    const float* Wg      = (const float*)d_in[9];
    const float* bg      = (const float*)d_in[10];
    float* out = (float*)d_out;

    k_init<<<(KK * NN + 255) / 256, 256>>>();
    k_deg<<<dim3((EE + 255) / 256, KK), 256>>>(ei);
    k_scanA<<<dim3(CHUNKS, KK), 256>>>();
    k_scanB<<<1, 128>>>();
    k_scanC<<<dim3(CHUNKS, KK), 256>>>();
    k_gemm1<<<dim3((NN + 127) / 128), 512>>>(flatten, W1);   // needs g_dis
    k_csr<<<dim3((EE + 255) / 256, KK), 256>>>(ei);
    k_agg1<<<dim3((NN + 31) / 32, KK), 256>>>(b1);
    k_lnfinal<<<1, 256>>>(gamma, beta, W2);
    k_h2<<<dim3((NN + 255) / 256, KK), 256>>>();
    k_agg2<<<dim3((NN + 255) / 256, KK), 256>>>(b2);
    k_final<<<(NN + 7) / 8, 256>>>(moe, Wg, bg, out);
}

// round 6
// speedup vs baseline: 1.2310x; 1.0265x over previous
#include <cuda_runtime.h>
#include <cuda_bf16.h>
#include <cstdint>

#define NN 100000
#define KK 4
#define EE 1600000
#define HH 64
#define FF 256
#define CHUNKS 98   // ceil(N/1024)

// ---------------- scratch (device globals; no runtime alloc) ----------------
__device__ uint32_t g_h[(size_t)KK * NN * 32];   // h' = dis*(flatten@W1), bf16x2 packed
__device__ uint32_t g_x[(size_t)KK * NN * 32];   // relu(conv1), bf16x2 packed
__device__ int   g_deg[KK * NN];
__device__ float g_dis[KK * NN];
__device__ int   g_rowstart[KK * (NN + 1)];
__device__ int   g_cursor[KK * NN];
__device__ int   g_csrc[(size_t)KK * EE];
__device__ float g_h2[(size_t)KK * NN * 2];      // h2' = dis * (x @ w2eff + c0)
__device__ float g_logits[(size_t)KK * NN * 2];
__device__ float g_sums[KK * HH];
__device__ float g_sumsq[KK * HH];
__device__ float g_w2eff[KK * HH * 2];
__device__ float g_c0[KK * 2];
__device__ int   g_partials[KK * CHUNKS];

// ---------------- helpers ----------------
__device__ __forceinline__ uint32_t f2tf(float f) {
    uint32_t u;
    asm("cvt.rna.tf32.f32 %0, %1;" : "=r"(u) : "f"(f));
    return u;
}
__device__ __forceinline__ uint32_t pack_bf2(float a, float b) {
    __nv_bfloat162 v = __floats2bfloat162_rn(a, b);
    return *(uint32_t*)&v;
}
__device__ __forceinline__ float2 unpack_bf2(uint32_t u) {
    __nv_bfloat162 v = *(__nv_bfloat162*)&u;
    return __bfloat1622float2(v);
}

// ---------------- init ----------------
__global__ void k_init() {
    int i = blockIdx.x * blockDim.x + threadIdx.x;
    if (i < KK * NN) g_deg[i] = 0;
    if (i < KK * HH) { g_sums[i] = 0.f; g_sumsq[i] = 0.f; }
    if (i < KK) g_rowstart[i * (NN + 1) + NN] = EE;
}

// ---------------- degree histogram ----------------
__global__ void k_deg(const int* __restrict__ ei) {
    int k = blockIdx.y;
    int e = blockIdx.x * blockDim.x + threadIdx.x;
    if (e >= EE) return;
    int dst = ei[(size_t)k * 2 * EE + EE + e];
    atomicAdd(&g_deg[k * NN + dst], 1);
}

// ---------------- exclusive scan of deg (3 kernels) ----------------
__global__ void k_scanA() {
    int k = blockIdx.y, chunk = blockIdx.x, t = threadIdx.x;
    int n0 = chunk * 1024 + t * 4;
    int s = 0;
#pragma unroll
    for (int i = 0; i < 4; i++) { int n = n0 + i; if (n < NN) s += g_deg[k * NN + n]; }
    for (int off = 16; off; off >>= 1) s += __shfl_down_sync(0xffffffffu, s, off);
    __shared__ int ws[8];
    if ((t & 31) == 0) ws[t >> 5] = s;
    __syncthreads();
    if (t == 0) {
        int tot = 0;
        for (int i = 0; i < 8; i++) tot += ws[i];
        g_partials[k * CHUNKS + chunk] = tot;
    }
}

__global__ void k_scanB() {
    int t = threadIdx.x;  // 128
    __shared__ int sm[128];
    for (int k = 0; k < KK; k++) {
        int p = (t < CHUNKS) ? g_partials[k * CHUNKS + t] : 0;
        sm[t] = p; __syncthreads();
        for (int off = 1; off < 128; off <<= 1) {
            int a = (t >= off) ? sm[t - off] : 0;
            __syncthreads();
            sm[t] += a;
            __syncthreads();
        }
        if (t < CHUNKS) g_partials[k * CHUNKS + t] = sm[t] - p;  // exclusive
        __syncthreads();
    }
}

__global__ void k_scanC() {
    int k = blockIdx.y, chunk = blockIdx.x, t = threadIdx.x;
    int lane = t & 31, wid = t >> 5;
    int n0 = chunk * 1024 + t * 4;
    int v[4];
#pragma unroll
    for (int i = 0; i < 4; i++) { int n = n0 + i; v[i] = (n < NN) ? g_deg[k * NN + n] : 0; }
    int s0 = v[0], s1 = s0 + v[1], s2 = s1 + v[2], s3 = s2 + v[3];
    int x = s3;
    for (int off = 1; off < 32; off <<= 1) {
        int y = __shfl_up_sync(0xffffffffu, x, off);
        if (lane >= off) x += y;
    }
    __shared__ int ws[8];
    if (lane == 31) ws[wid] = x;
    __syncthreads();
    if (t < 8) {
        int w = ws[t];
        for (int off = 1; off < 8; off <<= 1) {
            int y = __shfl_up_sync(0xffu, w, off);
            if (t >= off) w += y;
        }
        ws[t] = w;
    }
    __syncthreads();
    int excl = ((wid == 0) ? 0 : ws[wid - 1]) + (x - s3);
    int gbase = g_partials[k * CHUNKS + chunk] + excl;
    int pre[4] = {0, s0, s1, s2};
#pragma unroll
    for (int i = 0; i < 4; i++) {
        int n = n0 + i;
        if (n < NN) {
            int rs = gbase + pre[i];
            g_rowstart[k * (NN + 1) + n] = rs;
            g_cursor[k * NN + n] = rs;
            g_dis[k * NN + n] = rsqrtf((float)v[i] + 2.0f);
        }
    }
}

// ---------------- GEMM1: h'[k] = dis[k] * (flatten @ W1[k])  (tf32 mma.sync) ----
// block 128(M) x 256(N = all 4 experts) x K-tiles of 16; 16 warps (4x4), warp 32x64
#define ASTR 20
#define BSTR 264
__global__ __launch_bounds__(512) void k_gemm1(const float* __restrict__ A,
                                               const float* __restrict__ W1) {
    __shared__ float As[128 * ASTR];
    __shared__ float Bs[16 * BSTR];
    int t = threadIdx.x, lane = t & 31, warp = t >> 5;
    int wm = warp & 3, wn = warp >> 2;     // wn = expert index (warp n-tile = 64 = one expert)
    int bm = blockIdx.x;

    int ar = t >> 2, ac = (t & 3) * 4;     // A: 1 float4 per thread per tile
    int b0r = t >> 6,          b0q = (t & 63) * 4;
    int b1r = (t + 512) >> 6,  b1q = (t & 63) * 4;
    int b0k = b0q >> 6, b0h = b0q & 63;
    int b1k = b1q >> 6, b1h = b1q & 63;

    float4 rA, rB0, rB1;
    {
        int r0 = bm * 128 + ar;
        rA  = (r0 < NN) ? *(const float4*)(A + (size_t)r0 * FF + ac) : make_float4(0,0,0,0);
        rB0 = *(const float4*)(W1 + ((size_t)b0k * FF + b0r) * HH + b0h);
        rB1 = *(const float4*)(W1 + ((size_t)b1k * FF + b1r) * HH + b1h);
    }

    float c[2][8][4];
#pragma unroll
    for (int mi = 0; mi < 2; mi++)
#pragma unroll
        for (int ni = 0; ni < 8; ni++)
#pragma unroll
            for (int j = 0; j < 4; j++) c[mi][ni][j] = 0.f;

    for (int kt = 0; kt < 16; kt++) {
        *(float4*)(As + ar * ASTR + ac) = rA;
        *(float4*)(Bs + b0r * BSTR + b0q) = rB0;
        *(float4*)(Bs + b1r * BSTR + b1q) = rB1;
        __syncthreads();

        if (kt < 15) {
            int kn = (kt + 1) * 16;
            int r0 = bm * 128 + ar;
            rA  = (r0 < NN) ? *(const float4*)(A + (size_t)r0 * FF + kn + ac) : make_float4(0,0,0,0);
            rB0 = *(const float4*)(W1 + ((size_t)b0k * FF + kn + b0r) * HH + b0h);
            rB1 = *(const float4*)(W1 + ((size_t)b1k * FF + kn + b1r) * HH + b1h);
        }

#pragma unroll
        for (int kk = 0; kk < 16; kk += 8) {
            uint32_t af[2][4], bf[8][2];
#pragma unroll
            for (int mi = 0; mi < 2; mi++) {
                int r = wm * 32 + mi * 16 + (lane >> 2);
                int cc = kk + (lane & 3);
                af[mi][0] = f2tf(As[r * ASTR + cc]);
                af[mi][1] = f2tf(As[(r + 8) * ASTR + cc]);
                af[mi][2] = f2tf(As[r * ASTR + cc + 4]);
                af[mi][3] = f2tf(As[(r + 8) * ASTR + cc + 4]);
            }
#pragma unroll
            for (int ni = 0; ni < 8; ni++) {
                int col = wn * 64 + ni * 8 + (lane >> 2);
                int kr = kk + (lane & 3);
                bf[ni][0] = f2tf(Bs[kr * BSTR + col]);
                bf[ni][1] = f2tf(Bs[(kr + 4) * BSTR + col]);
            }
#pragma unroll
            for (int mi = 0; mi < 2; mi++)
#pragma unroll
                for (int ni = 0; ni < 8; ni++) {
                    asm volatile(
                        "mma.sync.aligned.m16n8k8.row.col.f32.tf32.tf32.f32 "
                        "{%0,%1,%2,%3}, {%4,%5,%6,%7}, {%8,%9}, {%0,%1,%2,%3};"
                        : "+f"(c[mi][ni][0]), "+f"(c[mi][ni][1]),
                          "+f"(c[mi][ni][2]), "+f"(c[mi][ni][3])
                        : "r"(af[mi][0]), "r"(af[mi][1]), "r"(af[mi][2]), "r"(af[mi][3]),
                          "r"(bf[ni][0]), "r"(bf[ni][1]));
                }
        }
        __syncthreads();
    }

    // epilogue: scale rows by dis[expert][row], pack to bf16x2; expert = wn
    uint32_t* hk = g_h + (size_t)wn * NN * 32;
    const float* dk = g_dis + wn * NN;
#pragma unroll
    for (int mi = 0; mi < 2; mi++) {
        int r0 = bm * 128 + wm * 32 + mi * 16 + (lane >> 2);
        int r1 = r0 + 8;
        float s0 = (r0 < NN) ? dk[r0] : 0.f;
        float s1 = (r1 < NN) ? dk[r1] : 0.f;
#pragma unroll
        for (int ni = 0; ni < 8; ni++) {
            int w = ni * 4 + (lane & 3);   // bf16x2 word index within row (32 words)
            if (r0 < NN) hk[(size_t)r0 * 32 + w] = pack_bf2(c[mi][ni][0] * s0, c[mi][ni][1] * s0);
            if (r1 < NN) hk[(size_t)r1 * 32 + w] = pack_bf2(c[mi][ni][2] * s1, c[mi][ni][3] * s1);
        }
    }
}

// ---------------- CSR fill ----------------
__global__ void k_csr(const int* __restrict__ ei) {
    int k = blockIdx.y;
    int e = blockIdx.x * blockDim.x + threadIdx.x;
    if (e >= EE) return;
    int src = ei[(size_t)k * 2 * EE + e];
    int dst = ei[(size_t)k * 2 * EE + EE + e];
    int pos = atomicAdd(&g_cursor[k * NN + dst], 1);
    g_csrc[(size_t)k * EE + pos] = src;
}

// ------- conv1 aggregate + bias + relu -> x (bf16x2), with fused LN stats -------
// warp per node-quad: each warp handles 4 nodes, lane owns features 2l, 2l+1
__global__ __launch_bounds__(256) void k_agg1(const float* __restrict__ b1) {
    int k = blockIdx.y;
    int t = threadIdx.x, lane = t & 31, warp = t >> 5;
    __shared__ float ss[64], sq[64];
    if (t < 64) { ss[t] = 0.f; sq[t] = 0.f; }
    __syncthreads();
    const uint32_t* hk = g_h + (size_t)k * NN * 32;
    const int* cs = g_csrc + (size_t)k * EE;
    const int* rs = g_rowstart + k * (NN + 1);
    const float* dk = g_dis + k * NN;
    float bx = b1[k * HH + 2 * lane];
    float by = b1[k * HH + 2 * lane + 1];
    float ls0 = 0.f, ls1 = 0.f, lq0 = 0.f, lq1 = 0.f;

#pragma unroll
    for (int i = 0; i < 4; i++) {
        int node = blockIdx.x * 32 + warp * 4 + i;
        if (node >= NN) break;
        int base = rs[node], end = rs[node + 1];
        float ax = 0.f, ay = 0.f;
        for (int i0 = base; i0 < end; i0 += 32) {
            int e = i0 + lane;
            int s = (e < end) ? cs[e] : 0;
            int cnt = min(32, end - i0);
            for (int j = 0; j < cnt; j++) {
                int sj = __shfl_sync(0xffffffffu, s, j);
                float2 hv = unpack_bf2(hk[(size_t)sj * 32 + lane]);
                ax += hv.x;
                ay += hv.y;
            }
        }
        float dn = dk[node];
        float2 hn = unpack_bf2(hk[(size_t)node * 32 + lane]);
        float sx = fmaxf(dn * (ax + 2.f * hn.x) + bx, 0.f);
        float sy = fmaxf(dn * (ay + 2.f * hn.y) + by, 0.f);
        g_x[((size_t)k * NN + node) * 32 + lane] = pack_bf2(sx, sy);
        ls0 += sx; lq0 += sx * sx;
        ls1 += sy; lq1 += sy * sy;
    }
    atomicAdd(&ss[2 * lane], ls0);
    atomicAdd(&ss[2 * lane + 1], ls1);
    atomicAdd(&sq[2 * lane], lq0);
    atomicAdd(&sq[2 * lane + 1], lq1);
    __syncthreads();
    if (t < 64) atomicAdd(&g_sums[k * HH + t], ss[t]);
    else if (t < 128) atomicAdd(&g_sumsq[k * HH + t - 64], sq[t - 64]);
}

// ---------------- fold LN into W2: w2eff = s*W2, c0 = t @ W2 ----------------
__global__ void k_lnfinal(const float* __restrict__ gamma, const float* __restrict__ beta,
                          const float* __restrict__ W2) {
    int t = threadIdx.x;  // 256
    int k = t >> 6, f = t & 63;
    float mu = g_sums[k * HH + f] / (float)NN;
    float var = g_sumsq[k * HH + f] / (float)NN - mu * mu;
    float inv = rsqrtf(var + 1e-5f);
    float s = inv * gamma[k * HH + f];
    float tt = beta[k * HH + f] - mu * s;
    float w0 = W2[k * HH * 2 + f * 2 + 0];
    float w1 = W2[k * HH * 2 + f * 2 + 1];
    g_w2eff[k * HH * 2 + f * 2 + 0] = s * w0;
    g_w2eff[k * HH * 2 + f * 2 + 1] = s * w1;
    __shared__ float red[256];
    red[t] = tt * w0; __syncthreads();
    for (int off = 32; off >= 1; off >>= 1) { if (f < off) red[t] += red[t + off]; __syncthreads(); }
    if (f == 0) g_c0[k * 2 + 0] = red[t];
    __syncthreads();
    red[t] = tt * w1; __syncthreads();
    for (int off = 32; off >= 1; off >>= 1) { if (f < off) red[t] += red[t + off]; __syncthreads(); }
    if (f == 0) g_c0[k * 2 + 1] = red[t];
}

// ---------------- h2' = dis * (relu_x @ w2eff + c0) ----------------
__global__ void k_h2() {
    int k = blockIdx.y;
    int t = threadIdx.x;
    __shared__ float w_s[128];
    __shared__ float c0s[2];
    if (t < 128) w_s[t] = g_w2eff[k * 128 + t];
    if (t < 2) c0s[t] = g_c0[k * 2 + t];
    __syncthreads();
    int n = blockIdx.x * blockDim.x + t;
    if (n >= NN) return;
    const uint32_t* xr = g_x + ((size_t)k * NN + n) * 32;
    float a0 = c0s[0], a1 = c0s[1];
#pragma unroll
    for (int w = 0; w < 32; w += 4) {
        uint4 q = *(const uint4*)(xr + w);
        float2 f0 = unpack_bf2(q.x), f1 = unpack_bf2(q.y);
        float2 f2 = unpack_bf2(q.z), f3 = unpack_bf2(q.w);
        a0 += f0.x * w_s[4*w]      + f0.y * w_s[4*w + 2]
            + f1.x * w_s[4*w + 4]  + f1.y * w_s[4*w + 6]
            + f2.x * w_s[4*w + 8]  + f2.y * w_s[4*w + 10]
            + f3.x * w_s[4*w + 12] + f3.y * w_s[4*w + 14];
        a1 += f0.x * w_s[4*w + 1]  + f0.y * w_s[4*w + 3]
            + f1.x * w_s[4*w + 5]  + f1.y * w_s[4*w + 7]
            + f2.x * w_s[4*w + 9]  + f2.y * w_s[4*w + 11]
            + f3.x * w_s[4*w + 13] + f3.y * w_s[4*w + 15];
    }
    float dn = g_dis[k * NN + n];
    g_h2[((size_t)k * NN + n) * 2 + 0] = a0 * dn;
    g_h2[((size_t)k * NN + n) * 2 + 1] = a1 * dn;
}

// ---------------- conv2 aggregate -> logits ----------------
__global__ void k_agg2(const float* __restrict__ b2) {
    int k = blockIdx.y;
    int n = blockIdx.x * blockDim.x + threadIdx.x;
    if (n >= NN) return;
    int base = g_rowstart[k * (NN + 1) + n];
    int end  = g_rowstart[k * (NN + 1) + n + 1];
    const int* cs = g_csrc + (size_t)k * EE;
    const float2* h2k = (const float2*)(g_h2 + (size_t)k * NN * 2);
    float a0 = 0.f, a1 = 0.f;
    for (int e = base; e < end; e++) {
        float2 hv = h2k[cs[e]];
        a0 += hv.x;
        a1 += hv.y;
    }
    float dn = g_dis[k * NN + n];
    float2 hn = h2k[n];
    a0 = dn * (a0 + 2.f * hn.x) + b2[k * 2 + 0];
    a1 = dn * (a1 + 2.f * hn.y) + b2[k * 2 + 1];
    g_logits[((size_t)k * NN + n) * 2 + 0] = a0;
    g_logits[((size_t)k * NN + n) * 2 + 1] = a1;
}

// ---------------- gating + softmax mix ----------------
__global__ __launch_bounds__(256) void k_final(const float* __restrict__ mf,
                                               const float* __restrict__ Wg,
                                               const float* __restrict__ bg,
                                               float* __restrict__ out) {
    __shared__ float wg_s[FF * KK];
    __shared__ float bg_s[KK];
    int t = threadIdx.x;
    for (int i = t; i < FF * KK; i += 256) wg_s[i] = Wg[i];
    if (t < KK) bg_s[t] = bg[t];
    __syncthreads();
    int lane = t & 31;
    int node = blockIdx.x * 8 + (t >> 5);
    if (node >= NN) return;
    const float* row = mf + (size_t)node * FF;
    float a0 = 0.f, a1 = 0.f, a2 = 0.f, a3 = 0.f;
#pragma unroll
    for (int j = 0; j < 8; j++) {
        float v = row[lane + 32 * j];
        const float* w = &wg_s[(lane + 32 * j) * 4];
        a0 += v * w[0]; a1 += v * w[1]; a2 += v * w[2]; a3 += v * w[3];
    }
    for (int off = 16; off; off >>= 1) {
        a0 += __shfl_xor_sync(0xffffffffu, a0, off);
        a1 += __shfl_xor_sync(0xffffffffu, a1, off);
        a2 += __shfl_xor_sync(0xffffffffu, a2, off);
        a3 += __shfl_xor_sync(0xffffffffu, a3, off);
    }
    float l0 = a0 + bg_s[0], l1 = a1 + bg_s[1], l2 = a2 + bg_s[2], l3 = a3 + bg_s[3];
    float m = fmaxf(fmaxf(l0, l1), fmaxf(l2, l3));
    float e0 = expf(l0 - m), e1 = expf(l1 - m), e2 = expf(l2 - m), e3 = expf(l3 - m);
    float Z = e0 + e1 + e2 + e3;
    float wk[4] = {e0 / Z, e1 / Z, e2 / Z, e3 / Z};
    float r0 = 0.f, r1 = 0.f, p0 = 0.f, p1 = 0.f;
#pragma unroll
    for (int k = 0; k < KK; k++) {
        float la = g_logits[((size_t)k * NN + node) * 2 + 0];
        float lb = g_logits[((size_t)k * NN + node) * 2 + 1];
        float mm = fmaxf(la, lb);
        float ea = expf(la - mm), eb = expf(lb - mm);
        float z = ea + eb;
        float lse = mm + logf(z);
        r0 += wk[k] * (la - lse);
        r1 += wk[k] * (lb - lse);
        p0 += wk[k] * (ea / z);
        p1 += wk[k] * (eb / z);
    }
    if (lane == 0) {
        out[(size_t)node * 2 + 0] = r0;
        out[(size_t)node * 2 + 1] = r1;
        out[(size_t)2 * NN + node * 2 + 0] = p0;
        out[(size_t)2 * NN + node * 2 + 1] = p1;
    }
}

// ---------------- launch ----------------
extern "C" void kernel_launch(void* const* d_in, const int* in_sizes, int n_in,
                              void* d_out, int out_size) {
    const float* flatten = (const float*)d_in[0];
    const float* moe     = (const float*)d_in[1];
    const int*   ei      = (const int*)d_in[2];
    const float* W1      = (const float*)d_in[3];
    const float* b1      = (const float*)d_in[4];
    const float* gamma   = (const float*)d_in[5];
    const float* beta    = (const float*)d_in[6];
    const float* W2      = (const float*)d_in[7];
    const float* b2      = (const float*)d_in[8];
    const float* Wg      = (const float*)d_in[9];
    const float* bg      = (const float*)d_in[10];
    float* out = (float*)d_out;

    k_init<<<(KK * NN + 255) / 256, 256>>>();
    k_deg<<<dim3((EE + 255) / 256, KK), 256>>>(ei);
    k_scanA<<<dim3(CHUNKS, KK), 256>>>();
    k_scanB<<<1, 128>>>();
    k_scanC<<<dim3(CHUNKS, KK), 256>>>();
    k_gemm1<<<dim3((NN + 127) / 128), 512>>>(flatten, W1);   // needs g_dis
    k_csr<<<dim3((EE + 255) / 256, KK), 256>>>(ei);
    k_agg1<<<dim3((NN + 31) / 32, KK), 256>>>(b1);
    k_lnfinal<<<1, 256>>>(gamma, beta, W2);
    k_h2<<<dim3((NN + 255) / 256, KK), 256>>>();
    k_agg2<<<dim3((NN + 255) / 256, KK), 256>>>(b2);
    k_final<<<(NN + 7) / 8, 256>>>(moe, Wg, bg, out);
}

// round 10
// speedup vs baseline: 1.4679x; 1.1925x over previous
#include <cuda_runtime.h>
#include <cuda_bf16.h>
#include <cstdint>

#define NN 100000
#define KK 4
#define EE 1600000
#define HH 64
#define FF 256
#define CHUNKS 98   // ceil(N/1024)

// ---------------- scratch (device globals; no runtime alloc) ----------------
__device__ uint32_t g_h[(size_t)KK * NN * 32];   // h' = dis*(flatten@W1), bf16x2 packed
__device__ uint32_t g_x[(size_t)KK * NN * 32];   // relu(conv1), bf16x2 packed
__device__ int   g_deg[KK * NN];
__device__ float g_dis[KK * NN];
__device__ int   g_rowstart[KK * (NN + 1)];
__device__ int   g_cursor[KK * NN];
__device__ int   g_csrc[(size_t)KK * EE];
__device__ float g_h2[(size_t)KK * NN * 2];      // h2' = dis * (x @ w2eff + c0)
__device__ float g_logits[(size_t)KK * NN * 2];
__device__ float g_gate[(size_t)NN * 4];
__device__ float g_sums[KK * HH];
__device__ float g_sumsq[KK * HH];
__device__ float g_w2eff[KK * HH * 2];
__device__ float g_c0[KK * 2];
__device__ int   g_partials[KK * CHUNKS];

// ---------------- helpers ----------------
__device__ __forceinline__ uint32_t f2tf(float f) {
    uint32_t u;
    asm("cvt.rna.tf32.f32 %0, %1;" : "=r"(u) : "f"(f));
    return u;
}
__device__ __forceinline__ uint32_t pack_bf2(float a, float b) {
    __nv_bfloat162 v = __floats2bfloat162_rn(a, b);
    return *(uint32_t*)&v;
}
__device__ __forceinline__ float2 unpack_bf2(uint32_t u) {
    __nv_bfloat162 v = *(__nv_bfloat162*)&u;
    return __bfloat1622float2(v);
}

// ---------------- init ----------------
__global__ void k_init() {
    int i = blockIdx.x * blockDim.x + threadIdx.x;
    if (i < KK * NN) g_deg[i] = 0;
    if (i < KK * HH) { g_sums[i] = 0.f; g_sumsq[i] = 0.f; }
    if (i < KK) g_rowstart[i * (NN + 1) + NN] = EE;
}

// ---------------- degree histogram ----------------
__global__ void k_deg(const int* __restrict__ ei) {
    int k = blockIdx.y;
    int e = blockIdx.x * blockDim.x + threadIdx.x;
    if (e >= EE) return;
    int dst = ei[(size_t)k * 2 * EE + EE + e];
    atomicAdd(&g_deg[k * NN + dst], 1);
}

// ---------------- exclusive scan of deg (3 kernels) ----------------
__global__ void k_scanA() {
    int k = blockIdx.y, chunk = blockIdx.x, t = threadIdx.x;
    int n0 = chunk * 1024 + t * 4;
    int s = 0;
#pragma unroll
    for (int i = 0; i < 4; i++) { int n = n0 + i; if (n < NN) s += g_deg[k * NN + n]; }
    for (int off = 16; off; off >>= 1) s += __shfl_down_sync(0xffffffffu, s, off);
    __shared__ int ws[8];
    if ((t & 31) == 0) ws[t >> 5] = s;
    __syncthreads();
    if (t == 0) {
        int tot = 0;
        for (int i = 0; i < 8; i++) tot += ws[i];
        g_partials[k * CHUNKS + chunk] = tot;
    }
}

__global__ void k_scanB() {
    int t = threadIdx.x;  // 128
    __shared__ int sm[128];
    for (int k = 0; k < KK; k++) {
        int p = (t < CHUNKS) ? g_partials[k * CHUNKS + t] : 0;
        sm[t] = p; __syncthreads();
        for (int off = 1; off < 128; off <<= 1) {
            int a = (t >= off) ? sm[t - off] : 0;
            __syncthreads();
            sm[t] += a;
            __syncthreads();
        }
        if (t < CHUNKS) g_partials[k * CHUNKS + t] = sm[t] - p;  // exclusive
        __syncthreads();
    }
}

__global__ void k_scanC() {
    int k = blockIdx.y, chunk = blockIdx.x, t = threadIdx.x;
    int lane = t & 31, wid = t >> 5;
    int n0 = chunk * 1024 + t * 4;
    int v[4];
#pragma unroll
    for (int i = 0; i < 4; i++) { int n = n0 + i; v[i] = (n < NN) ? g_deg[k * NN + n] : 0; }
    int s0 = v[0], s1 = s0 + v[1], s2 = s1 + v[2], s3 = s2 + v[3];
    int x = s3;
    for (int off = 1; off < 32; off <<= 1) {
        int y = __shfl_up_sync(0xffffffffu, x, off);
        if (lane >= off) x += y;
    }
    __shared__ int ws[8];
    if (lane == 31) ws[wid] = x;
    __syncthreads();
    if (t < 8) {
        int w = ws[t];
        for (int off = 1; off < 8; off <<= 1) {
            int y = __shfl_up_sync(0xffu, w, off);
            if (t >= off) w += y;
        }
        ws[t] = w;
    }
    __syncthreads();
    int excl = ((wid == 0) ? 0 : ws[wid - 1]) + (x - s3);
    int gbase = g_partials[k * CHUNKS + chunk] + excl;
    int pre[4] = {0, s0, s1, s2};
#pragma unroll
    for (int i = 0; i < 4; i++) {
        int n = n0 + i;
        if (n < NN) {
            int rs = gbase + pre[i];
            g_rowstart[k * (NN + 1) + n] = rs;
            g_cursor[k * NN + n] = rs;
            g_dis[k * NN + n] = rsqrtf((float)v[i] + 2.0f);
        }
    }
}

// ---------------- GEMM1: h'[k] = dis[k] * (flatten @ W1[k])  (tf32 mma.sync) ----
// block 128(M) x 256(N = all 4 experts) x K-tiles of 16; 16 warps (4x4), warp 32x64
// tf32 rounding applied once at smem-fill (numerically identical to read-side cvt)
#define ASTR 20
#define BSTR 264
__global__ __launch_bounds__(512) void k_gemm1(const float* __restrict__ A,
                                               const float* __restrict__ W1) {
    __shared__ uint32_t As[128 * ASTR];
    __shared__ uint32_t Bs[16 * BSTR];
    int t = threadIdx.x, lane = t & 31, warp = t >> 5;
    int wm = warp & 3, wn = warp >> 2;     // wn = expert index (warp n-tile = 64 = one expert)
    int bm = blockIdx.x;

    int ar = t >> 2, ac = (t & 3) * 4;
    int b0r = t >> 6,          b0q = (t & 63) * 4;
    int b1r = (t + 512) >> 6,  b1q = (t & 63) * 4;
    int b0k = b0q >> 6, b0h = b0q & 63;
    int b1k = b1q >> 6, b1h = b1q & 63;

    float4 rA, rB0, rB1;
    {
        int r0 = bm * 128 + ar;
        rA  = (r0 < NN) ? *(const float4*)(A + (size_t)r0 * FF + ac) : make_float4(0,0,0,0);
        rB0 = *(const float4*)(W1 + ((size_t)b0k * FF + b0r) * HH + b0h);
        rB1 = *(const float4*)(W1 + ((size_t)b1k * FF + b1r) * HH + b1h);
    }

    float c[2][8][4];
#pragma unroll
    for (int mi = 0; mi < 2; mi++)
#pragma unroll
        for (int ni = 0; ni < 8; ni++)
#pragma unroll
            for (int j = 0; j < 4; j++) c[mi][ni][j] = 0.f;

    for (int kt = 0; kt < 16; kt++) {
        As[ar * ASTR + ac + 0] = f2tf(rA.x);
        As[ar * ASTR + ac + 1] = f2tf(rA.y);
        As[ar * ASTR + ac + 2] = f2tf(rA.z);
        As[ar * ASTR + ac + 3] = f2tf(rA.w);
        Bs[b0r * BSTR + b0q + 0] = f2tf(rB0.x);
        Bs[b0r * BSTR + b0q + 1] = f2tf(rB0.y);
        Bs[b0r * BSTR + b0q + 2] = f2tf(rB0.z);
        Bs[b0r * BSTR + b0q + 3] = f2tf(rB0.w);
        Bs[b1r * BSTR + b1q + 0] = f2tf(rB1.x);
        Bs[b1r * BSTR + b1q + 1] = f2tf(rB1.y);
        Bs[b1r * BSTR + b1q + 2] = f2tf(rB1.z);
        Bs[b1r * BSTR + b1q + 3] = f2tf(rB1.w);
        __syncthreads();

        if (kt < 15) {
            int kn = (kt + 1) * 16;
            int r0 = bm * 128 + ar;
            rA  = (r0 < NN) ? *(const float4*)(A + (size_t)r0 * FF + kn + ac) : make_float4(0,0,0,0);
            rB0 = *(const float4*)(W1 + ((size_t)b0k * FF + kn + b0r) * HH + b0h);
            rB1 = *(const float4*)(W1 + ((size_t)b1k * FF + kn + b1r) * HH + b1h);
        }

#pragma unroll
        for (int kk = 0; kk < 16; kk += 8) {
            uint32_t af[2][4], bf[8][2];
#pragma unroll
            for (int mi = 0; mi < 2; mi++) {
                int r = wm * 32 + mi * 16 + (lane >> 2);
                int cc = kk + (lane & 3);
                af[mi][0] = As[r * ASTR + cc];
                af[mi][1] = As[(r + 8) * ASTR + cc];
                af[mi][2] = As[r * ASTR + cc + 4];
                af[mi][3] = As[(r + 8) * ASTR + cc + 4];
            }
#pragma unroll
            for (int ni = 0; ni < 8; ni++) {
                int col = wn * 64 + ni * 8 + (lane >> 2);
                int kr = kk + (lane & 3);
                bf[ni][0] = Bs[kr * BSTR + col];
                bf[ni][1] = Bs[(kr + 4) * BSTR + col];
            }
#pragma unroll
            for (int mi = 0; mi < 2; mi++)
#pragma unroll
                for (int ni = 0; ni < 8; ni++) {
                    asm volatile(
                        "mma.sync.aligned.m16n8k8.row.col.f32.tf32.tf32.f32 "
                        "{%0,%1,%2,%3}, {%4,%5,%6,%7}, {%8,%9}, {%0,%1,%2,%3};"
                        : "+f"(c[mi][ni][0]), "+f"(c[mi][ni][1]),
                          "+f"(c[mi][ni][2]), "+f"(c[mi][ni][3])
                        : "r"(af[mi][0]), "r"(af[mi][1]), "r"(af[mi][2]), "r"(af[mi][3]),
                          "r"(bf[ni][0]), "r"(bf[ni][1]));
                }
        }
        __syncthreads();
    }

    // epilogue: scale rows by dis[expert][row], pack to bf16x2; expert = wn
    uint32_t* hk = g_h + (size_t)wn * NN * 32;
    const float* dk = g_dis + wn * NN;
#pragma unroll
    for (int mi = 0; mi < 2; mi++) {
        int r0 = bm * 128 + wm * 32 + mi * 16 + (lane >> 2);
        int r1 = r0 + 8;
        float s0 = (r0 < NN) ? dk[r0] : 0.f;
        float s1 = (r1 < NN) ? dk[r1] : 0.f;
#pragma unroll
        for (int ni = 0; ni < 8; ni++) {
            int w = ni * 4 + (lane & 3);   // bf16x2 word index within row (32 words)
            if (r0 < NN) hk[(size_t)r0 * 32 + w] = pack_bf2(c[mi][ni][0] * s0, c[mi][ni][1] * s0);
            if (r1 < NN) hk[(size_t)r1 * 32 + w] = pack_bf2(c[mi][ni][2] * s1, c[mi][ni][3] * s1);
        }
    }
}

// ---------------- CSR fill ----------------
__global__ void k_csr(const int* __restrict__ ei) {
    int k = blockIdx.y;
    int e = blockIdx.x * blockDim.x + threadIdx.x;
    if (e >= EE) return;
    int src = ei[(size_t)k * 2 * EE + e];
    int dst = ei[(size_t)k * 2 * EE + EE + e];
    int pos = atomicAdd(&g_cursor[k * NN + dst], 1);
    g_csrc[(size_t)k * EE + pos] = src;
}

// ------- conv1 aggregate + bias + relu -> x (bf16x2), fused LN stats -------
// half-warp (16 lanes) per node; lane owns 4 features (uint2 = 2 bf16x2 words);
// no shuffles: src indices loaded broadcast from L1; 4-wide unrolled gather.
__global__ __launch_bounds__(256) void k_agg1(const float* __restrict__ b1) {
    int k = blockIdx.y;
    int t = threadIdx.x, l16 = t & 15, hw = t >> 4;   // 16 half-warps
    __shared__ float ss[64], sq[64];
    if (t < 64) { ss[t] = 0.f; sq[t] = 0.f; }
    __syncthreads();
    const uint32_t* hk = g_h + (size_t)k * NN * 32;
    const int* cs = g_csrc + (size_t)k * EE;
    const int* rs = g_rowstart + k * (NN + 1);
    const float* dk = g_dis + k * NN;
    float4 bv = *(const float4*)(b1 + k * HH + 4 * l16);
    int w0 = 2 * l16;
    float ts0 = 0.f, ts1 = 0.f, ts2 = 0.f, ts3 = 0.f;
    float tq0 = 0.f, tq1 = 0.f, tq2 = 0.f, tq3 = 0.f;

#pragma unroll
    for (int i = 0; i < 4; i++) {
        int node = blockIdx.x * 64 + hw * 4 + i;
        if (node >= NN) break;
        int base = rs[node], end = rs[node + 1];
        float a0 = 0.f, a1 = 0.f, a2 = 0.f, a3 = 0.f;
        int e = base;
        for (; e + 4 <= end; e += 4) {
            int i0 = __ldg(cs + e), i1 = __ldg(cs + e + 1);
            int i2 = __ldg(cs + e + 2), i3 = __ldg(cs + e + 3);
            uint2 r0 = *(const uint2*)(hk + (size_t)i0 * 32 + w0);
            uint2 r1 = *(const uint2*)(hk + (size_t)i1 * 32 + w0);
            uint2 r2 = *(const uint2*)(hk + (size_t)i2 * 32 + w0);
            uint2 r3 = *(const uint2*)(hk + (size_t)i3 * 32 + w0);
            float2 f;
            f = unpack_bf2(r0.x); a0 += f.x; a1 += f.y;
            f = unpack_bf2(r0.y); a2 += f.x; a3 += f.y;
            f = unpack_bf2(r1.x); a0 += f.x; a1 += f.y;
            f = unpack_bf2(r1.y); a2 += f.x; a3 += f.y;
            f = unpack_bf2(r2.x); a0 += f.x; a1 += f.y;
            f = unpack_bf2(r2.y); a2 += f.x; a3 += f.y;
            f = unpack_bf2(r3.x); a0 += f.x; a1 += f.y;
            f = unpack_bf2(r3.y); a2 += f.x; a3 += f.y;
        }
        for (; e < end; e++) {
            int s = __ldg(cs + e);
            uint2 r = *(const uint2*)(hk + (size_t)s * 32 + w0);
            float2 f;
            f = unpack_bf2(r.x); a0 += f.x; a1 += f.y;
            f = unpack_bf2(r.y); a2 += f.x; a3 += f.y;
        }
        float dn = dk[node];
        uint2 hn = *(const uint2*)(hk + (size_t)node * 32 + w0);
        float2 h0 = unpack_bf2(hn.x), h1 = unpack_bf2(hn.y);
        float x0 = fmaxf(dn * (a0 + 2.f * h0.x) + bv.x, 0.f);
        float x1 = fmaxf(dn * (a1 + 2.f * h0.y) + bv.y, 0.f);
        float x2 = fmaxf(dn * (a2 + 2.f * h1.x) + bv.z, 0.f);
        float x3 = fmaxf(dn * (a3 + 2.f * h1.y) + bv.w, 0.f);
        *(uint2*)(g_x + ((size_t)k * NN + node) * 32 + w0) =
            make_uint2(pack_bf2(x0, x1), pack_bf2(x2, x3));
        ts0 += x0; tq0 += x0 * x0;
        ts1 += x1; tq1 += x1 * x1;
        ts2 += x2; tq2 += x2 * x2;
        ts3 += x3; tq3 += x3 * x3;
    }
    atomicAdd(&ss[4 * l16 + 0], ts0);
    atomicAdd(&ss[4 * l16 + 1], ts1);
    atomicAdd(&ss[4 * l16 + 2], ts2);
    atomicAdd(&ss[4 * l16 + 3], ts3);
    atomicAdd(&sq[4 * l16 + 0], tq0);
    atomicAdd(&sq[4 * l16 + 1], tq1);
    atomicAdd(&sq[4 * l16 + 2], tq2);
    atomicAdd(&sq[4 * l16 + 3], tq3);
    __syncthreads();
    if (t < 64) atomicAdd(&g_sums[k * HH + t], ss[t]);
    else if (t < 128) atomicAdd(&g_sumsq[k * HH + t - 64], sq[t - 64]);
}

// ---------------- fold LN into W2: w2eff = s*W2, c0 = t @ W2 ----------------
__global__ void k_lnfinal(const float* __restrict__ gamma, const float* __restrict__ beta,
                          const float* __restrict__ W2) {
    int t = threadIdx.x;  // 256
    int k = t >> 6, f = t & 63;
    float mu = g_sums[k * HH + f] / (float)NN;
    float var = g_sumsq[k * HH + f] / (float)NN - mu * mu;
    float inv = rsqrtf(var + 1e-5f);
    float s = inv * gamma[k * HH + f];
    float tt = beta[k * HH + f] - mu * s;
    float w0 = W2[k * HH * 2 + f * 2 + 0];
    float w1 = W2[k * HH * 2 + f * 2 + 1];
    g_w2eff[k * HH * 2 + f * 2 + 0] = s * w0;
    g_w2eff[k * HH * 2 + f * 2 + 1] = s * w1;
    __shared__ float red[256];
    red[t] = tt * w0; __syncthreads();
    for (int off = 32; off >= 1; off >>= 1) { if (f < off) red[t] += red[t + off]; __syncthreads(); }
    if (f == 0) g_c0[k * 2 + 0] = red[t];
    __syncthreads();
    red[t] = tt * w1; __syncthreads();
    for (int off = 32; off >= 1; off >>= 1) { if (f < off) red[t] += red[t + off]; __syncthreads(); }
    if (f == 0) g_c0[k * 2 + 1] = red[t];
}

// ---------------- h2' = dis * (relu_x @ w2eff + c0) ----------------
__global__ void k_h2() {
    int k = blockIdx.y;
    int t = threadIdx.x;
    __shared__ float w_s[128];
    __shared__ float c0s[2];
    if (t < 128) w_s[t] = g_w2eff[k * 128 + t];
    if (t < 2) c0s[t] = g_c0[k * 2 + t];
    __syncthreads();
    int n = blockIdx.x * blockDim.x + t;
    if (n >= NN) return;
    const uint32_t* xr = g_x + ((size_t)k * NN + n) * 32;
    float a0 = c0s[0], a1 = c0s[1];
#pragma unroll
    for (int w = 0; w < 32; w += 4) {
        uint4 q = *(const uint4*)(xr + w);
        float2 f0 = unpack_bf2(q.x), f1 = unpack_bf2(q.y);
        float2 f2 = unpack_bf2(q.z), f3 = unpack_bf2(q.w);
        a0 += f0.x * w_s[4*w]      + f0.y * w_s[4*w + 2]
            + f1.x * w_s[4*w + 4]  + f1.y * w_s[4*w + 6]
            + f2.x * w_s[4*w + 8]  + f2.y * w_s[4*w + 10]
            + f3.x * w_s[4*w + 12] + f3.y * w_s[4*w + 14];
        a1 += f0.x * w_s[4*w + 1]  + f0.y * w_s[4*w + 3]
            + f1.x * w_s[4*w + 5]  + f1.y * w_s[4*w + 7]
            + f2.x * w_s[4*w + 9]  + f2.y * w_s[4*w + 11]
            + f3.x * w_s[4*w + 13] + f3.y * w_s[4*w + 15];
    }
    float dn = g_dis[k * NN + n];
    g_h2[((size_t)k * NN + n) * 2 + 0] = a0 * dn;
    g_h2[((size_t)k * NN + n) * 2 + 1] = a1 * dn;
}

// ---------------- conv2 aggregate -> logits ----------------
__global__ void k_agg2(const float* __restrict__ b2) {
    int k = blockIdx.y;
    int n = blockIdx.x * blockDim.x + threadIdx.x;
    if (n >= NN) return;
    int base = g_rowstart[k * (NN + 1) + n];
    int end  = g_rowstart[k * (NN + 1) + n + 1];
    const int* cs = g_csrc + (size_t)k * EE;
    const float2* h2k = (const float2*)(g_h2 + (size_t)k * NN * 2);
    float a0 = 0.f, a1 = 0.f;
    int e = base;
    for (; e + 4 <= end; e += 4) {
        int i0 = __ldg(cs + e), i1 = __ldg(cs + e + 1);
        int i2 = __ldg(cs + e + 2), i3 = __ldg(cs + e + 3);
        float2 v0 = h2k[i0], v1 = h2k[i1], v2 = h2k[i2], v3 = h2k[i3];
        a0 += v0.x + v1.x + v2.x + v3.x;
        a1 += v0.y + v1.y + v2.y + v3.y;
    }
    for (; e < end; e++) {
        float2 hv = h2k[__ldg(cs + e)];
        a0 += hv.x;
        a1 += hv.y;
    }
    float dn = g_dis[k * NN + n];
    float2 hn = h2k[n];
    a0 = dn * (a0 + 2.f * hn.x) + b2[k * 2 + 0];
    a1 = dn * (a1 + 2.f * hn.y) + b2[k * 2 + 1];
    g_logits[((size_t)k * NN + n) * 2 + 0] = a0;
    g_logits[((size_t)k * NN + n) * 2 + 1] = a1;
}

// ---------------- gating weights (independent; runs early on stream 2) ----------
__global__ __launch_bounds__(256) void k_gate(const float* __restrict__ mf,
                                              const float* __restrict__ Wg,
                                              const float* __restrict__ bg) {
    __shared__ float wg_s[FF * KK];
    __shared__ float bg_s[KK];
    int t = threadIdx.x;
    for (int i = t; i < FF * KK; i += 256) wg_s[i] = Wg[i];
    if (t < KK) bg_s[t] = bg[t];
    __syncthreads();
    int lane = t & 31;
    int node = blockIdx.x * 8 + (t >> 5);
    if (node >= NN) return;
    const float* row = mf + (size_t)node * FF;
    float a0 = 0.f, a1 = 0.f, a2 = 0.f, a3 = 0.f;
#pragma unroll
    for (int j = 0; j < 8; j++) {
        float v = row[lane + 32 * j];
        const float* w = &wg_s[(lane + 32 * j) * 4];
        a0 += v * w[0]; a1 += v * w[1]; a2 += v * w[2]; a3 += v * w[3];
    }
    for (int off = 16; off; off >>= 1) {
        a0 += __shfl_xor_sync(0xffffffffu, a0, off);
        a1 += __shfl_xor_sync(0xffffffffu, a1, off);
        a2 += __shfl_xor_sync(0xffffffffu, a2, off);
        a3 += __shfl_xor_sync(0xffffffffu, a3, off);
    }
    if (lane == 0) {
        float l0 = a0 + bg_s[0], l1 = a1 + bg_s[1], l2 = a2 + bg_s[2], l3 = a3 + bg_s[3];
        float m = fmaxf(fmaxf(l0, l1), fmaxf(l2, l3));
        float e0 = expf(l0 - m), e1 = expf(l1 - m), e2 = expf(l2 - m), e3 = expf(l3 - m);
        float Z = 1.f / (e0 + e1 + e2 + e3);
        *(float4*)(g_gate + (size_t)node * 4) = make_float4(e0 * Z, e1 * Z, e2 * Z, e3 * Z);
    }
}

// ---------------- final mix (thread per node) ----------------
__global__ void k_final(float* __restrict__ out) {
    int node = blockIdx.x * blockDim.x + threadIdx.x;
    if (node >= NN) return;
    float4 wv = *(const float4*)(g_gate + (size_t)node * 4);
    float wk[4] = {wv.x, wv.y, wv.z, wv.w};
    float r0 = 0.f, r1 = 0.f, p0 = 0.f, p1 = 0.f;
#pragma unroll
    for (int k = 0; k < KK; k++) {
        float la = g_logits[((size_t)k * NN + node) * 2 + 0];
        float lb = g_logits[((size_t)k * NN + node) * 2 + 1];
        float mm = fmaxf(la, lb);
        float ea = expf(la - mm), eb = expf(lb - mm);
        float z = ea + eb;
        float lse = mm + logf(z);
        r0 += wk[k] * (la - lse);
        r1 += wk[k] * (lb - lse);
        p0 += wk[k] * (ea / z);
        p1 += wk[k] * (eb / z);
    }
    out[(size_t)node * 2 + 0] = r0;
    out[(size_t)node * 2 + 1] = r1;
    out[(size_t)2 * NN + node * 2 + 0] = p0;
    out[(size_t)2 * NN + node * 2 + 1] = p1;
}

// ---------------- launch ----------------
static cudaStream_t s2 = nullptr;
static cudaEvent_t ev0 = nullptr, evC = nullptr, evG = nullptr;

extern "C" void kernel_launch(void* const* d_in, const int* in_sizes, int n_in,
                              void* d_out, int out_size) {
    const float* flatten = (const float*)d_in[0];
    const float* moe     = (const float*)d_in[1];
    const int*   ei      = (const int*)d_in[2];
    const float* W1      = (const float*)d_in[3];
    const float* b1      = (const float*)d_in[4];
    const float* gamma   = (const float*)d_in[5];
    const float* beta    = (const float*)d_in[6];
    const float* W2      = (const float*)d_in[7];
    const float* b2      = (const float*)d_in[8];
    const float* Wg      = (const float*)d_in[9];
    const float* bg      = (const float*)d_in[10];
    float* out = (float*)d_out;

    if (s2 == nullptr) {
        cudaStreamCreateWithFlags(&s2, cudaStreamNonBlocking);
        cudaEventCreateWithFlags(&ev0, cudaEventDisableTiming);
        cudaEventCreateWithFlags(&evC, cudaEventDisableTiming);
        cudaEventCreateWithFlags(&evG, cudaEventDisableTiming);
    }

    // main stream (legacy default)
    k_init<<<(KK * NN + 255) / 256, 256>>>();
    cudaEventRecord(ev0, 0);

    // side stream: gating GEMV (independent), later GEMM1
    cudaStreamWaitEvent(s2, ev0, 0);
    k_gate<<<(NN + 7) / 8, 256, 0, s2>>>(moe, Wg, bg);

    k_deg<<<dim3((EE + 255) / 256, KK), 256>>>(ei);
    k_scanA<<<dim3(CHUNKS, KK), 256>>>();
    k_scanB<<<1, 128>>>();
    k_scanC<<<dim3(CHUNKS, KK), 256>>>();
    cudaEventRecord(evC, 0);

    // GEMM1 needs g_dis (scanC); runs concurrent with CSR fill
    cudaStreamWaitEvent(s2, evC, 0);
    k_gemm1<<<dim3((NN + 127) / 128), 512, 0, s2>>>(flatten, W1);
    cudaEventRecord(evG, s2);

    k_csr<<<dim3((EE + 255) / 256, KK), 256>>>(ei);

    cudaStreamWaitEvent(0, evG, 0);   // join: agg1 needs g_h + g_csrc
    k_agg1<<<dim3((NN + 63) / 64, KK), 256>>>(b1);
    k_lnfinal<<<1, 256>>>(gamma, beta, W2);
    k_h2<<<dim3((NN + 255) / 256, KK), 256>>>();
    k_agg2<<<dim3((NN + 255) / 256, KK), 256>>>(b2);
    k_final<<<(NN + 255) / 256, 256>>>(out);
}